// round 5
// baseline (speedup 1.0000x reference)
#include <cuda_runtime.h>
#include <cstdint>

// ---------------- problem constants ----------------
#define N_NODES 50000
#define N_PAD   50048          // multiple of 128
#define E_EDGES 800000
#define R_REL   8
#define B_BASES 8
#define H_DIM   128
#define L_LAYERS 3
#define FDIM    6
#define K_TOT   1152           // R*H + H
#define BN_EPS  1e-5f
#define KCHUNK  32
#define NCHUNKS 36             // K_TOT / KCHUNK
#define SMPAD   36             // 32 + 4 pad floats per row
#define GEMM_SMEM (4 * 128 * SMPAD * 4)   // 2 stages * (A + B) * 128 rows * 36 floats

#define NR       (N_NODES * R_REL)        // 400000 segments
#define SCAN_EPB 1024
#define SCAN_NB  ((NR + SCAN_EPB - 1) / SCAN_EPB)   // 391

// ---------------- scratch (device globals) ----------------
__device__ float g_A[(size_t)N_PAD * K_TOT];     // [n][0..1023]=scaled sums, [1024..1151]=x residual
__device__ float g_WT[(size_t)H_DIM * K_TOT];    // fused weight, transposed: [o][k] (tf32-rounded)
__device__ float g_h[(size_t)N_PAD * H_DIM];     // raw GEMM output (pre-BN; bias dropped, BN cancels it)
__device__ int   g_cnt[NR];                      // per-(dst,rel) edge counts
__device__ int   g_off[NR + 1];                  // CSR segment offsets
__device__ int   g_cursor[NR];                   // bucket cursors for sort
__device__ int   g_bsum[SCAN_NB];                // scan block sums
__device__ int   g_esrc[E_EDGES];                // src ids sorted by (dst,rel)
__device__ float g_chs[H_DIM];
__device__ float g_chq[H_DIM];

// ---------------- helpers ----------------
__device__ __forceinline__ void cpa16(uint32_t dst, const void* src) {
    asm volatile("cp.async.cg.shared.global [%0], [%1], 16;" :: "r"(dst), "l"(src) : "memory");
}
__device__ __forceinline__ uint32_t smem_u32(const void* p) {
    uint32_t a;
    asm("{ .reg .u64 t; cvta.to.shared.u64 t, %1; cvt.u32.u64 %0, t; }" : "=r"(a) : "l"(p));
    return a;
}
__device__ __forceinline__ float round_tf32(float x) {
    float r;
    asm("cvt.rna.tf32.f32 %0, %1;" : "=f"(r) : "f"(x));
    return r;
}
__device__ __forceinline__ void mma_tf32(float& c0, float& c1, float& c2, float& c3,
                                         uint32_t a0, uint32_t a1, uint32_t a2, uint32_t a3,
                                         uint32_t b0, uint32_t b1) {
    asm volatile("mma.sync.aligned.m16n8k8.row.col.f32.tf32.tf32.f32 "
                 "{%0,%1,%2,%3}, {%4,%5,%6,%7}, {%8,%9}, {%0,%1,%2,%3};"
                 : "+f"(c0), "+f"(c1), "+f"(c2), "+f"(c3)
                 : "r"(a0), "r"(a1), "r"(a2), "r"(a3), "r"(b0), "r"(b1));
}

// ---------------- setup: histogram + scan + sort ----------------
__global__ void k_count(const int* __restrict__ ei, const int* __restrict__ et) {
    int e = blockIdx.x * blockDim.x + threadIdx.x;
    if (e < E_EDGES) atomicAdd(&g_cnt[ei[E_EDGES + e] * R_REL + et[e]], 1);
}

// exclusive scan over g_cnt[NR] -> g_off. 1024 elems/block (4/thread).
__global__ void k_scan1() {
    __shared__ int ts[256];
    int b = blockIdx.x, t = threadIdx.x;
    int base = b * SCAN_EPB + t * 4;
    int v0 = 0, v1 = 0, v2 = 0, v3 = 0;
    if (base + 4 <= NR) {
        int4 c = *reinterpret_cast<const int4*>(g_cnt + base);
        v0 = c.x; v1 = c.y; v2 = c.z; v3 = c.w;
    }
    int tsum = v0 + v1 + v2 + v3;
    ts[t] = tsum;
    __syncthreads();
#pragma unroll
    for (int o = 1; o < 256; o <<= 1) {
        int x = (t >= o) ? ts[t - o] : 0;
        __syncthreads();
        ts[t] += x;
        __syncthreads();
    }
    int texcl = ts[t] - tsum;
    if (base + 4 <= NR) {
        g_off[base + 0] = texcl;
        g_off[base + 1] = texcl + v0;
        g_off[base + 2] = texcl + v0 + v1;
        g_off[base + 3] = texcl + v0 + v1 + v2;
    }
    if (t == 255) g_bsum[b] = ts[255];
}
__global__ void k_scan2() {
    __shared__ int s[512];
    int t = threadIdx.x;
    int v = (t < SCAN_NB) ? g_bsum[t] : 0;
    s[t] = v;
    __syncthreads();
#pragma unroll
    for (int o = 1; o < 512; o <<= 1) {
        int x = (t >= o) ? s[t - o] : 0;
        __syncthreads();
        s[t] += x;
        __syncthreads();
    }
    if (t < SCAN_NB) g_bsum[t] = s[t] - v;   // exclusive
}
__global__ void k_scan3() {
    int b = blockIdx.x, t = threadIdx.x;
    int add = g_bsum[b];
    int base = b * SCAN_EPB + t * 4;
#pragma unroll
    for (int j = 0; j < 4; j++) {
        int i = base + j;
        if (i < NR) {
            int v = g_off[i] + add;
            g_off[i] = v;
            g_cursor[i] = v;
        }
    }
    if (b == 0 && t == 0) g_off[NR] = E_EDGES;
}
__global__ void k_sortedge(const int* __restrict__ ei, const int* __restrict__ et) {
    int e = blockIdx.x * blockDim.x + threadIdx.x;
    if (e >= E_EDGES) return;
    int seg = ei[E_EDGES + e] * R_REL + et[e];
    int pos = atomicAdd(&g_cursor[seg], 1);
    g_esrc[pos] = ei[e];
}

// ---------------- init residual ----------------
__global__ void k_init(const int* __restrict__ xids, const float* __restrict__ nf,
                       const float* __restrict__ emb, const float* __restrict__ fw,
                       const float* __restrict__ fb, const float* __restrict__ vrt) {
    int n = blockIdx.x, h = threadIdx.x;
    __shared__ float f[FDIM];
    if (h < FDIM) f[h] = nf[n * FDIM + h];
    __syncthreads();
    float acc = fb[h];
#pragma unroll
    for (int d = 0; d < FDIM; d++) acc = fmaf(f[d], fw[h * FDIM + d], acc);
    g_A[(size_t)n * K_TOT + 1024 + h] = emb[(size_t)xids[n] * H_DIM + h] + fmaxf(acc, 0.0f) + vrt[h];
}

// fused transposed weight WT[o][k], tf32-rounded
__global__ void k_weights(const float* __restrict__ bases, const float* __restrict__ comp,
                          const float* __restrict__ root, int l) {
    int k = blockIdx.x * blockDim.x + threadIdx.x;   // 0..1151
    int o = blockIdx.y;                              // 0..127
    float v;
    if (k < R_REL * H_DIM) {
        int r = k >> 7, i = k & 127;
        v = 0.0f;
        const float* cp = comp + (l * R_REL + r) * B_BASES;
#pragma unroll
        for (int b = 0; b < B_BASES; b++)
            v = fmaf(cp[b], bases[(((size_t)l * B_BASES + b) * H_DIM + i) * H_DIM + o], v);
    } else {
        v = root[((size_t)l * H_DIM + (k - 1024)) * H_DIM + o];
    }
    g_WT[(size_t)o * K_TOT + k] = round_tf32(v);
}

// ---------------- segmented aggregation (replaces zero + scatter) -------------
// one block per dst node, 128 threads = h channels. For each relation segment,
// mean of x[src] rows; writes the full 1024-col sums region (zeros included).
__global__ __launch_bounds__(128, 8) void k_agg() {
    int n = blockIdx.x, h = threadIdx.x;
    float* outp = g_A + (size_t)n * K_TOT;
    int base = n * R_REL;
    int s = g_off[base];
#pragma unroll
    for (int r = 0; r < R_REL; r++) {
        int e2 = g_off[base + r + 1];
        int c = e2 - s;
        float inv = 1.0f / (float)(c > 1 ? c : 1);
        float acc = 0.0f;
        int i = s;
        for (; i + 4 <= e2; i += 4) {
            int s0 = g_esrc[i], s1 = g_esrc[i + 1], s2 = g_esrc[i + 2], s3 = g_esrc[i + 3];
            float a0 = g_A[(size_t)s0 * K_TOT + 1024 + h];
            float a1 = g_A[(size_t)s1 * K_TOT + 1024 + h];
            float a2 = g_A[(size_t)s2 * K_TOT + 1024 + h];
            float a3 = g_A[(size_t)s3 * K_TOT + 1024 + h];
            acc += (a0 + a1) + (a2 + a3);
        }
        for (; i < e2; i++)
            acc += g_A[(size_t)g_esrc[i] * K_TOT + 1024 + h];
        outp[r * H_DIM + h] = acc * inv;
        s = e2;
    }
}

// ---------------- tf32 mma.sync GEMM: g_h = A[N_PAD x 1152] @ WT^T -------------
__global__ __launch_bounds__(256, 2) void k_gemm() {
    extern __shared__ float sm[];
    float* As = sm;
    float* Bs = sm + 2 * 128 * SMPAD;

    const int tid  = threadIdx.x;
    const int wid  = tid >> 5;
    const int lane = tid & 31;
    const int gID  = lane >> 2;
    const int tg   = lane & 3;
    const int wm   = wid & 1;
    const int wn   = wid >> 1;
    const int bm   = blockIdx.x * 128;

    const int lrow = tid >> 2;
    const int lc4  = tid & 3;

    const float* aptr  = g_A + (size_t)(bm + lrow) * K_TOT;
    const float* aptr2 = aptr + (size_t)64 * K_TOT;
    const float* bptr  = g_WT + (size_t)lrow * K_TOT;
    const float* bptr2 = bptr + (size_t)64 * K_TOT;

    uint32_t as_base = smem_u32(As);
    uint32_t bs_base = smem_u32(Bs);

    float acc[4][4][4];
#pragma unroll
    for (int i = 0; i < 4; i++)
#pragma unroll
        for (int j = 0; j < 4; j++)
#pragma unroll
            for (int q = 0; q < 4; q++) acc[i][j][q] = 0.0f;

    auto load_chunk = [&](int t, int s) {
        uint32_t ad = as_base + (uint32_t)(s * 128 * SMPAD) * 4;
        uint32_t bd = bs_base + (uint32_t)(s * 128 * SMPAD) * 4;
        int ko = t * KCHUNK;
#pragma unroll
        for (int hh = 0; hh < 2; hh++) {
            int c = lc4 * 4 + hh * 16;
            cpa16(ad + (uint32_t)((lrow)      * SMPAD + c) * 4, aptr  + ko + c);
            cpa16(ad + (uint32_t)((lrow + 64) * SMPAD + c) * 4, aptr2 + ko + c);
            cpa16(bd + (uint32_t)((lrow)      * SMPAD + c) * 4, bptr  + ko + c);
            cpa16(bd + (uint32_t)((lrow + 64) * SMPAD + c) * 4, bptr2 + ko + c);
        }
        asm volatile("cp.async.commit_group;" ::: "memory");
    };

    load_chunk(0, 0);

    for (int t = 0; t < NCHUNKS; t++) {
        int s = t & 1;
        if (t + 1 < NCHUNKS) {
            load_chunk(t + 1, s ^ 1);
            asm volatile("cp.async.wait_group 1;" ::: "memory");
        } else {
            asm volatile("cp.async.wait_group 0;" ::: "memory");
        }
        __syncthreads();

        const float* Asb = As + s * 128 * SMPAD;
        const float* Bsb = Bs + s * 128 * SMPAD;
#pragma unroll
        for (int ks = 0; ks < 4; ks++) {
            uint32_t bf[4][2];
#pragma unroll
            for (int nt = 0; nt < 4; nt++) {
                const float* bp = Bsb + (wn * 32 + nt * 8 + gID) * SMPAD + ks * 8 + tg;
                bf[nt][0] = __float_as_uint(bp[0]);
                bf[nt][1] = __float_as_uint(bp[4]);
            }
#pragma unroll
            for (int mt = 0; mt < 4; mt++) {
                const float* ap = Asb + (wm * 64 + mt * 16 + gID) * SMPAD + ks * 8 + tg;
                uint32_t a0 = __float_as_uint(ap[0]);
                uint32_t a1 = __float_as_uint(ap[8 * SMPAD]);
                uint32_t a2 = __float_as_uint(ap[4]);
                uint32_t a3 = __float_as_uint(ap[8 * SMPAD + 4]);
#pragma unroll
                for (int nt = 0; nt < 4; nt++)
                    mma_tf32(acc[mt][nt][0], acc[mt][nt][1], acc[mt][nt][2], acc[mt][nt][3],
                             a0, a1, a2, a3, bf[nt][0], bf[nt][1]);
            }
        }
        __syncthreads();
    }

    // epilogue: store h + fused BN column stats
    float colS[4][2], colQ[4][2];
#pragma unroll
    for (int nt = 0; nt < 4; nt++)
#pragma unroll
        for (int j = 0; j < 2; j++) { colS[nt][j] = 0.0f; colQ[nt][j] = 0.0f; }

#pragma unroll
    for (int mt = 0; mt < 4; mt++) {
        int row0 = bm + wm * 64 + mt * 16 + gID;
        int row1 = row0 + 8;
#pragma unroll
        for (int nt = 0; nt < 4; nt++) {
            int col = wn * 32 + nt * 8 + tg * 2;
            float c0 = acc[mt][nt][0], c1 = acc[mt][nt][1];
            float c2 = acc[mt][nt][2], c3 = acc[mt][nt][3];
            *reinterpret_cast<float2*>(g_h + (size_t)row0 * H_DIM + col) = make_float2(c0, c1);
            *reinterpret_cast<float2*>(g_h + (size_t)row1 * H_DIM + col) = make_float2(c2, c3);
            if (row0 < N_NODES) {
                colS[nt][0] += c0; colQ[nt][0] += c0 * c0;
                colS[nt][1] += c1; colQ[nt][1] += c1 * c1;
            }
            if (row1 < N_NODES) {
                colS[nt][0] += c2; colQ[nt][0] += c2 * c2;
                colS[nt][1] += c3; colQ[nt][1] += c3 * c3;
            }
        }
    }
    __syncthreads();
    float* bns = sm;
    float* bnq = sm + 128;
    if (tid < 128) { bns[tid] = 0.0f; bnq[tid] = 0.0f; }
    __syncthreads();
#pragma unroll
    for (int nt = 0; nt < 4; nt++)
#pragma unroll
        for (int j = 0; j < 2; j++) {
            int col = wn * 32 + nt * 8 + tg * 2 + j;
            atomicAdd(&bns[col], colS[nt][j]);
            atomicAdd(&bnq[col], colQ[nt][j]);
        }
    __syncthreads();
    if (tid < 128) {
        atomicAdd(&g_chs[tid], bns[tid]);
        atomicAdd(&g_chq[tid], bnq[tid]);
    }
}

// ---------------- BN finalize + residual update ----------------
__global__ void k_bnstats() {
    int c = threadIdx.x;
    float mu  = g_chs[c] * (1.0f / N_NODES);
    float var = g_chq[c] * (1.0f / N_NODES) - mu * mu;
    g_chs[c] = mu;
    g_chq[c] = rsqrtf(var + BN_EPS);
}
__global__ void k_update(const float* __restrict__ gamma, const float* __restrict__ beta,
                         int l, float* __restrict__ out, int last) {
    int n = blockIdx.x, h = threadIdx.x;
    float v  = g_h[(size_t)n * H_DIM + h];
    float hn = gamma[l * H_DIM + h] * (v - g_chs[h]) * g_chq[h] + beta[l * H_DIM + h];
    float* xp = g_A + (size_t)n * K_TOT + 1024 + h;
    float nx = *xp + fmaxf(hn, 0.0f);
    *xp = nx;
    if (last) out[(size_t)n * H_DIM + h] = nx;
}

// ---------------- launch ----------------
extern "C" void kernel_launch(void* const* d_in, const int* in_sizes, int n_in,
                              void* d_out, int out_size) {
    const int*   x_ids = (const int*)  d_in[0];
    const int*   eidx  = (const int*)  d_in[1];
    const int*   etype = (const int*)  d_in[2];
    const float* nf    = (const float*)d_in[3];
    const float* emb   = (const float*)d_in[4];
    const float* fw    = (const float*)d_in[5];
    const float* fb    = (const float*)d_in[6];
    const float* vrt   = (const float*)d_in[7];
    const float* bases = (const float*)d_in[8];
    const float* comp  = (const float*)d_in[9];
    const float* root  = (const float*)d_in[10];
    const float* gamma = (const float*)d_in[12];
    const float* beta  = (const float*)d_in[13];
    float* out = (float*)d_out;

    cudaFuncSetAttribute(k_gemm, cudaFuncAttributeMaxDynamicSharedMemorySize, GEMM_SMEM);

    void *p_cnt, *p_chs, *p_chq;
    cudaGetSymbolAddress(&p_cnt, g_cnt);
    cudaGetSymbolAddress(&p_chs, g_chs);
    cudaGetSymbolAddress(&p_chq, g_chq);

    // setup: histogram -> scan -> bucket sort (topology is layer-invariant)
    cudaMemsetAsync(p_cnt, 0, sizeof(int) * NR, 0);
    k_count<<<(E_EDGES + 255) / 256, 256>>>(eidx, etype);
    k_scan1<<<SCAN_NB, 256>>>();
    k_scan2<<<1, 512>>>();
    k_scan3<<<SCAN_NB, 256>>>();
    k_sortedge<<<(E_EDGES + 255) / 256, 256>>>(eidx, etype);
    k_init<<<N_NODES, H_DIM>>>(x_ids, nf, emb, fw, fb, vrt);

    for (int l = 0; l < L_LAYERS; l++) {
        k_weights<<<dim3(9, 128), 128>>>(bases, comp, root, l);
        k_agg<<<N_NODES, H_DIM>>>();
        cudaMemsetAsync(p_chs, 0, sizeof(float) * H_DIM, 0);
        cudaMemsetAsync(p_chq, 0, sizeof(float) * H_DIM, 0);
        k_gemm<<<N_PAD / 128, 256, GEMM_SMEM>>>();
        k_bnstats<<<1, H_DIM>>>();
        k_update<<<N_NODES, H_DIM>>>(gamma, beta, l, out, l == L_LAYERS - 1);
    }
}

// round 7
// speedup vs baseline: 1.4882x; 1.4882x over previous
#include <cuda_runtime.h>
#include <cstdint>

// ---------------- problem constants ----------------
#define N_NODES 50000
#define N_PAD   50048          // multiple of 128
#define E_EDGES 800000
#define R_REL   8
#define B_BASES 8
#define H_DIM   128
#define L_LAYERS 3
#define FDIM    6
#define K_SUMS  1024           // R*H
#define K_TOT   1152           // R*H + H
#define BN_EPS  1e-5f
#define KCHUNK  32
#define NCHUNKS 36             // K_TOT / KCHUNK
#define SMPAD   36             // 32 + 4 pad floats per row
#define GEMM_SMEM (4 * 128 * SMPAD * 4)

#define NR       (N_NODES * R_REL)        // 400000 segments
#define SCAN_EPB 1024
#define SCAN_NB  ((NR + SCAN_EPB - 1) / SCAN_EPB)   // 391

// ---------------- scratch (device globals) ----------------
__device__ float g_S[(size_t)N_PAD * K_SUMS];    // per-(node,rel) means  (GEMM A, cols 0..1023)
__device__ float g_x[(size_t)N_PAD * H_DIM];     // residual stream       (GEMM A, cols 1024..1151)
__device__ float g_WT[(size_t)H_DIM * K_TOT];    // fused weight, transposed [o][k], tf32-rounded
__device__ float g_h[(size_t)N_PAD * H_DIM];     // raw GEMM output (pre-BN; bias dropped)
__device__ int   g_cnt[NR];
__device__ int   g_off[NR + 1];
__device__ int   g_cursor[NR];
__device__ int   g_bsum[SCAN_NB];
__device__ int   g_esrc[E_EDGES];                // src ids sorted by (dst,rel)
__device__ float g_chs[H_DIM];
__device__ float g_chq[H_DIM];

// ---------------- helpers ----------------
__device__ __forceinline__ void cpa16(uint32_t dst, const void* src) {
    asm volatile("cp.async.cg.shared.global [%0], [%1], 16;" :: "r"(dst), "l"(src) : "memory");
}
__device__ __forceinline__ uint32_t smem_u32(const void* p) {
    uint32_t a;
    asm("{ .reg .u64 t; cvta.to.shared.u64 t, %1; cvt.u32.u64 %0, t; }" : "=r"(a) : "l"(p));
    return a;
}
__device__ __forceinline__ float round_tf32(float x) {
    float r;
    asm("cvt.rna.tf32.f32 %0, %1;" : "=f"(r) : "f"(x));
    return r;
}
__device__ __forceinline__ void mma_tf32(float& c0, float& c1, float& c2, float& c3,
                                         uint32_t a0, uint32_t a1, uint32_t a2, uint32_t a3,
                                         uint32_t b0, uint32_t b1) {
    asm volatile("mma.sync.aligned.m16n8k8.row.col.f32.tf32.tf32.f32 "
                 "{%0,%1,%2,%3}, {%4,%5,%6,%7}, {%8,%9}, {%0,%1,%2,%3};"
                 : "+f"(c0), "+f"(c1), "+f"(c2), "+f"(c3)
                 : "r"(a0), "r"(a1), "r"(a2), "r"(a3), "r"(b0), "r"(b1));
}

// ---------------- setup: histogram + scan + bucket sort ----------------
__global__ void k_count(const int* __restrict__ ei, const int* __restrict__ et) {
    int e = blockIdx.x * blockDim.x + threadIdx.x;
    if (e < E_EDGES) atomicAdd(&g_cnt[ei[E_EDGES + e] * R_REL + et[e]], 1);
}
__global__ void k_scan1() {
    __shared__ int ts[256];
    int b = blockIdx.x, t = threadIdx.x;
    int base = b * SCAN_EPB + t * 4;
    int v0 = 0, v1 = 0, v2 = 0, v3 = 0;
    if (base + 4 <= NR) {
        int4 c = *reinterpret_cast<const int4*>(g_cnt + base);
        v0 = c.x; v1 = c.y; v2 = c.z; v3 = c.w;
    }
    int tsum = v0 + v1 + v2 + v3;
    ts[t] = tsum;
    __syncthreads();
#pragma unroll
    for (int o = 1; o < 256; o <<= 1) {
        int x = (t >= o) ? ts[t - o] : 0;
        __syncthreads();
        ts[t] += x;
        __syncthreads();
    }
    int texcl = ts[t] - tsum;
    if (base + 4 <= NR) {
        g_off[base + 0] = texcl;
        g_off[base + 1] = texcl + v0;
        g_off[base + 2] = texcl + v0 + v1;
        g_off[base + 3] = texcl + v0 + v1 + v2;
    }
    if (t == 255) g_bsum[b] = ts[255];
}
__global__ void k_scan2() {
    __shared__ int s[512];
    int t = threadIdx.x;
    int v = (t < SCAN_NB) ? g_bsum[t] : 0;
    s[t] = v;
    __syncthreads();
#pragma unroll
    for (int o = 1; o < 512; o <<= 1) {
        int x = (t >= o) ? s[t - o] : 0;
        __syncthreads();
        s[t] += x;
        __syncthreads();
    }
    if (t < SCAN_NB) g_bsum[t] = s[t] - v;   // exclusive
}
__global__ void k_scan3() {
    int b = blockIdx.x, t = threadIdx.x;
    int add = g_bsum[b];
    int base = b * SCAN_EPB + t * 4;
#pragma unroll
    for (int j = 0; j < 4; j++) {
        int i = base + j;
        if (i < NR) {
            int v = g_off[i] + add;
            g_off[i] = v;
            g_cursor[i] = v;
        }
    }
    if (b == 0 && t == 0) g_off[NR] = E_EDGES;
}
__global__ void k_sortedge(const int* __restrict__ ei, const int* __restrict__ et) {
    int e = blockIdx.x * blockDim.x + threadIdx.x;
    if (e >= E_EDGES) return;
    int seg = ei[E_EDGES + e] * R_REL + et[e];
    int pos = atomicAdd(&g_cursor[seg], 1);
    g_esrc[pos] = ei[e];
}

// ---------------- init residual ----------------
__global__ void k_init(const int* __restrict__ xids, const float* __restrict__ nf,
                       const float* __restrict__ emb, const float* __restrict__ fw,
                       const float* __restrict__ fb, const float* __restrict__ vrt) {
    int n = blockIdx.x, h = threadIdx.x;
    __shared__ float f[FDIM];
    if (h < FDIM) f[h] = nf[n * FDIM + h];
    __syncthreads();
    float acc = fb[h];
#pragma unroll
    for (int d = 0; d < FDIM; d++) acc = fmaf(f[d], fw[h * FDIM + d], acc);
    g_x[(size_t)n * H_DIM + h] = emb[(size_t)xids[n] * H_DIM + h] + fmaxf(acc, 0.0f) + vrt[h];
}

// fused transposed weight WT[o][k], tf32-rounded; block (0,0) also zeroes BN accumulators
__global__ void k_weights(const float* __restrict__ bases, const float* __restrict__ comp,
                          const float* __restrict__ root, int l) {
    if (blockIdx.x == 0 && blockIdx.y == 0) {
        int t = threadIdx.x;
        if (t < H_DIM) { g_chs[t] = 0.0f; g_chq[t] = 0.0f; }
    }
    int k = blockIdx.x * blockDim.x + threadIdx.x;   // 0..1151
    int o = blockIdx.y;                              // 0..127
    float v;
    if (k < K_SUMS) {
        int r = k >> 7, i = k & 127;
        v = 0.0f;
        const float* cp = comp + (l * R_REL + r) * B_BASES;
#pragma unroll
        for (int b = 0; b < B_BASES; b++)
            v = fmaf(cp[b], bases[(((size_t)l * B_BASES + b) * H_DIM + i) * H_DIM + o], v);
    } else {
        v = root[((size_t)l * H_DIM + (k - K_SUMS)) * H_DIM + o];
    }
    g_WT[(size_t)o * K_TOT + k] = round_tf32(v);
}

// ---------------- warp-per-segment gather (replaces zero + atomic scatter) ----
// one warp per (dst,rel) segment: mean of x[src] rows, plain float4 store.
// 512-thread blocks: 16 consecutive segments (= 2 dst nodes) share L1 for x rows.
// Empty segments store zeros (so no memset pass is ever needed).
__global__ __launch_bounds__(512, 4) void k_gather() {
    int gid  = (blockIdx.x * blockDim.x + threadIdx.x) >> 5;   // segment id
    int lane = threadIdx.x & 31;
    if (gid >= NR) return;
    int s = g_off[gid], e = g_off[gid + 1];
    int c = e - s;
    float4 acc = make_float4(0.0f, 0.0f, 0.0f, 0.0f);
    if (c > 0) {
        int i = s;
        for (; i + 4 <= e; i += 4) {
            int s0 = g_esrc[i], s1 = g_esrc[i + 1], s2 = g_esrc[i + 2], s3 = g_esrc[i + 3];
            float4 v0 = *reinterpret_cast<const float4*>(g_x + (size_t)s0 * H_DIM + lane * 4);
            float4 v1 = *reinterpret_cast<const float4*>(g_x + (size_t)s1 * H_DIM + lane * 4);
            float4 v2 = *reinterpret_cast<const float4*>(g_x + (size_t)s2 * H_DIM + lane * 4);
            float4 v3 = *reinterpret_cast<const float4*>(g_x + (size_t)s3 * H_DIM + lane * 4);
            acc.x += (v0.x + v1.x) + (v2.x + v3.x);
            acc.y += (v0.y + v1.y) + (v2.y + v3.y);
            acc.z += (v0.z + v1.z) + (v2.z + v3.z);
            acc.w += (v0.w + v1.w) + (v2.w + v3.w);
        }
        for (; i < e; i++) {
            float4 v = *reinterpret_cast<const float4*>(g_x + (size_t)g_esrc[i] * H_DIM + lane * 4);
            acc.x += v.x; acc.y += v.y; acc.z += v.z; acc.w += v.w;
        }
        float inv = 1.0f / (float)c;
        acc.x *= inv; acc.y *= inv; acc.z *= inv; acc.w *= inv;
    }
    *reinterpret_cast<float4*>(g_S + (size_t)gid * H_DIM + lane * 4) = acc;
}

// ---------------- tf32 mma.sync GEMM: g_h = [S | x] @ WT^T ---------------------
__global__ __launch_bounds__(256, 2) void k_gemm() {
    extern __shared__ float sm[];
    float* As = sm;
    float* Bs = sm + 2 * 128 * SMPAD;

    const int tid  = threadIdx.x;
    const int wid  = tid >> 5;
    const int lane = tid & 31;
    const int gID  = lane >> 2;
    const int tg   = lane & 3;
    const int wm   = wid & 1;
    const int wn   = wid >> 1;
    const int bm   = blockIdx.x * 128;

    const int lrow = tid >> 2;
    const int lc4  = tid & 3;

    const float* aS  = g_S + (size_t)(bm + lrow) * K_SUMS;
    const float* aS2 = aS + (size_t)64 * K_SUMS;
    const float* aX  = g_x + (size_t)(bm + lrow) * H_DIM;
    const float* aX2 = aX + (size_t)64 * H_DIM;
    const float* bptr  = g_WT + (size_t)lrow * K_TOT;
    const float* bptr2 = bptr + (size_t)64 * K_TOT;

    uint32_t as_base = smem_u32(As);
    uint32_t bs_base = smem_u32(Bs);

    float acc[4][4][4];
#pragma unroll
    for (int i = 0; i < 4; i++)
#pragma unroll
        for (int j = 0; j < 4; j++)
#pragma unroll
            for (int q = 0; q < 4; q++) acc[i][j][q] = 0.0f;

    auto load_chunk = [&](int t, int s) {
        uint32_t ad = as_base + (uint32_t)(s * 128 * SMPAD) * 4;
        uint32_t bd = bs_base + (uint32_t)(s * 128 * SMPAD) * 4;
        const float* a1 = (t < 32) ? (aS  + t * KCHUNK) : (aX  + (t - 32) * KCHUNK);
        const float* a2 = (t < 32) ? (aS2 + t * KCHUNK) : (aX2 + (t - 32) * KCHUNK);
        int ko = t * KCHUNK;
#pragma unroll
        for (int hh = 0; hh < 2; hh++) {
            int c = lc4 * 4 + hh * 16;
            cpa16(ad + (uint32_t)((lrow)      * SMPAD + c) * 4, a1 + c);
            cpa16(ad + (uint32_t)((lrow + 64) * SMPAD + c) * 4, a2 + c);
            cpa16(bd + (uint32_t)((lrow)      * SMPAD + c) * 4, bptr  + ko + c);
            cpa16(bd + (uint32_t)((lrow + 64) * SMPAD + c) * 4, bptr2 + ko + c);
        }
        asm volatile("cp.async.commit_group;" ::: "memory");
    };

    load_chunk(0, 0);

    for (int t = 0; t < NCHUNKS; t++) {
        int s = t & 1;
        if (t + 1 < NCHUNKS) {
            load_chunk(t + 1, s ^ 1);
            asm volatile("cp.async.wait_group 1;" ::: "memory");
        } else {
            asm volatile("cp.async.wait_group 0;" ::: "memory");
        }
        __syncthreads();

        const float* Asb = As + s * 128 * SMPAD;
        const float* Bsb = Bs + s * 128 * SMPAD;
#pragma unroll
        for (int ks = 0; ks < 4; ks++) {
            uint32_t bf[4][2];
#pragma unroll
            for (int nt = 0; nt < 4; nt++) {
                const float* bp = Bsb + (wn * 32 + nt * 8 + gID) * SMPAD + ks * 8 + tg;
                bf[nt][0] = __float_as_uint(bp[0]);
                bf[nt][1] = __float_as_uint(bp[4]);
            }
#pragma unroll
            for (int mt = 0; mt < 4; mt++) {
                const float* ap = Asb + (wm * 64 + mt * 16 + gID) * SMPAD + ks * 8 + tg;
                uint32_t a0 = __float_as_uint(ap[0]);
                uint32_t a1 = __float_as_uint(ap[8 * SMPAD]);
                uint32_t a2 = __float_as_uint(ap[4]);
                uint32_t a3 = __float_as_uint(ap[8 * SMPAD + 4]);
#pragma unroll
                for (int nt = 0; nt < 4; nt++)
                    mma_tf32(acc[mt][nt][0], acc[mt][nt][1], acc[mt][nt][2], acc[mt][nt][3],
                             a0, a1, a2, a3, bf[nt][0], bf[nt][1]);
            }
        }
        __syncthreads();
    }

    // epilogue: store h + fused BN column stats
    float colS[4][2], colQ[4][2];
#pragma unroll
    for (int nt = 0; nt < 4; nt++)
#pragma unroll
        for (int j = 0; j < 2; j++) { colS[nt][j] = 0.0f; colQ[nt][j] = 0.0f; }

#pragma unroll
    for (int mt = 0; mt < 4; mt++) {
        int row0 = bm + wm * 64 + mt * 16 + gID;
        int row1 = row0 + 8;
#pragma unroll
        for (int nt = 0; nt < 4; nt++) {
            int col = wn * 32 + nt * 8 + tg * 2;
            float c0 = acc[mt][nt][0], c1 = acc[mt][nt][1];
            float c2 = acc[mt][nt][2], c3 = acc[mt][nt][3];
            *reinterpret_cast<float2*>(g_h + (size_t)row0 * H_DIM + col) = make_float2(c0, c1);
            *reinterpret_cast<float2*>(g_h + (size_t)row1 * H_DIM + col) = make_float2(c2, c3);
            if (row0 < N_NODES) {
                colS[nt][0] += c0; colQ[nt][0] += c0 * c0;
                colS[nt][1] += c1; colQ[nt][1] += c1 * c1;
            }
            if (row1 < N_NODES) {
                colS[nt][0] += c2; colQ[nt][0] += c2 * c2;
                colS[nt][1] += c3; colQ[nt][1] += c3 * c3;
            }
        }
    }
    __syncthreads();
    float* bns = sm;
    float* bnq = sm + 128;
    if (tid < 128) { bns[tid] = 0.0f; bnq[tid] = 0.0f; }
    __syncthreads();
#pragma unroll
    for (int nt = 0; nt < 4; nt++)
#pragma unroll
        for (int j = 0; j < 2; j++) {
            int col = wn * 32 + nt * 8 + tg * 2 + j;
            atomicAdd(&bns[col], colS[nt][j]);
            atomicAdd(&bnq[col], colQ[nt][j]);
        }
    __syncthreads();
    if (tid < 128) {
        atomicAdd(&g_chs[tid], bns[tid]);
        atomicAdd(&g_chq[tid], bnq[tid]);
    }
}

// ---------------- BN finalize + residual update ----------------
__global__ void k_bnstats() {
    int c = threadIdx.x;
    float mu  = g_chs[c] * (1.0f / N_NODES);
    float var = g_chq[c] * (1.0f / N_NODES) - mu * mu;
    g_chs[c] = mu;
    g_chq[c] = rsqrtf(var + BN_EPS);
}
__global__ void k_update(const float* __restrict__ gamma, const float* __restrict__ beta,
                         int l, float* __restrict__ out, int last) {
    int n = blockIdx.x, h = threadIdx.x;
    float v  = g_h[(size_t)n * H_DIM + h];
    float hn = gamma[l * H_DIM + h] * (v - g_chs[h]) * g_chq[h] + beta[l * H_DIM + h];
    float* xp = g_x + (size_t)n * H_DIM + h;
    float nx = *xp + fmaxf(hn, 0.0f);
    *xp = nx;
    if (last) out[(size_t)n * H_DIM + h] = nx;
}

// ---------------- launch ----------------
extern "C" void kernel_launch(void* const* d_in, const int* in_sizes, int n_in,
                              void* d_out, int out_size) {
    const int*   x_ids = (const int*)  d_in[0];
    const int*   eidx  = (const int*)  d_in[1];
    const int*   etype = (const int*)  d_in[2];
    const float* nf    = (const float*)d_in[3];
    const float* emb   = (const float*)d_in[4];
    const float* fw    = (const float*)d_in[5];
    const float* fb    = (const float*)d_in[6];
    const float* vrt   = (const float*)d_in[7];
    const float* bases = (const float*)d_in[8];
    const float* comp  = (const float*)d_in[9];
    const float* root  = (const float*)d_in[10];
    const float* gamma = (const float*)d_in[12];
    const float* beta  = (const float*)d_in[13];
    float* out = (float*)d_out;

    cudaFuncSetAttribute(k_gemm, cudaFuncAttributeMaxDynamicSharedMemorySize, GEMM_SMEM);

    void* p_cnt;
    cudaGetSymbolAddress(&p_cnt, g_cnt);

    // one-time topology setup: histogram -> scan -> bucket sort
    cudaMemsetAsync(p_cnt, 0, sizeof(int) * NR, 0);
    k_count<<<(E_EDGES + 255) / 256, 256>>>(eidx, etype);
    k_scan1<<<SCAN_NB, 256>>>();
    k_scan2<<<1, 512>>>();
    k_scan3<<<SCAN_NB, 256>>>();
    k_sortedge<<<(E_EDGES + 255) / 256, 256>>>(eidx, etype);
    k_init<<<N_NODES, H_DIM>>>(x_ids, nf, emb, fw, fb, vrt);

    for (int l = 0; l < L_LAYERS; l++) {
        k_weights<<<dim3(9, 128), 128>>>(bases, comp, root, l);
        k_gather<<<NR / 16, 512>>>();
        k_gemm<<<N_PAD / 128, 256, GEMM_SMEM>>>();
        k_bnstats<<<1, H_DIM>>>();
        k_update<<<N_NODES, H_DIM>>>(gamma, beta, l, out, l == L_LAYERS - 1);
    }
}